// round 3
// baseline (speedup 1.0000x reference)
#include <cuda_runtime.h>
#include <math.h>

// ---------------- problem constants (compile-time from reference) ----------------
#define NB_B      8
#define NQH       32
#define NKVH      8
#define HD        128
#define GG        4          // NQH / NKVH
#define BPS       289        // blocks per seq
#define T_TOT     4086       // 4085 past tokens + 1 current
#define SPLITS    4
#define PER_SPLIT 1022       // ceil(4086/4)
#define CUR_POSI  4095
#define RS        8          // GEMM row splits

// ---------------- device scratch (static, allowed) ----------------
__device__ __align__(16) float d_cos[4096 * 64];
__device__ __align__(16) float d_sin[4096 * 64];
__device__ __align__(16) float d_qrs[NB_B * NQH * HD];                 // roped+scaled q
__device__ __align__(16) float d_pacc[SPLITS * NB_B * NKVH * GG * HD]; // split partial acc
__device__ float d_pm[SPLITS * NB_B * NKVH * GG];
__device__ float d_pl[SPLITS * NB_B * NKVH * GG];
__device__ __align__(16) float d_attn[NB_B * 4096];
__device__ __align__(16) float d_gpart[RS * NB_B * 4096];

// ---------------- rope tables: cos/sin[pos][freq], pos in [0,4096), freq in [0,64) ----
__global__ void k_tables() {
    int idx = blockIdx.x * blockDim.x + threadIdx.x;   // 262144 threads
    int pos = idx >> 6, f = idx & 63;
    double inv = pow(10000.0, -(double)f / 64.0);
    double ang = (double)pos * inv;
    double sd, cd;
    sincos(ang, &sd, &cd);
    d_cos[idx] = (float)cd;
    d_sin[idx] = (float)sd;
}

// ---------------- q rope at CUR_POS, folded softmax scale ----------------
__global__ void k_qrope(const float* __restrict__ q) {
    int head = blockIdx.x;      // b*32 + qhead
    int f = threadIdx.x;        // 0..63
    float x1 = q[head * HD + f];
    float x2 = q[head * HD + 64 + f];
    double inv = pow(10000.0, -(double)f / 64.0);
    double ang = (double)CUR_POSI * inv;
    double sd, cd; sincos(ang, &sd, &cd);
    float c = (float)cd, s = (float)sd;
    // 1/sqrt(128) * log2(e) : run softmax in exp2 domain
    const float SC = 0.08838834764831845f * 1.4426950408889634f;
    d_qrs[head * HD + f]      = (x1 * c - x2 * s) * SC;
    d_qrs[head * HD + 64 + f] = (x2 * c + x1 * s) * SC;
}

__device__ __forceinline__ float dot8(float4 a0, float4 a1, float4 b0, float4 b1) {
    return a0.x * b0.x + a0.y * b0.y + a0.z * b0.z + a0.w * b0.w
         + a1.x * b1.x + a1.y * b1.y + a1.z * b1.z + a1.w * b1.w;
}

// ---------------- flash-decode attention, split over T ----------------
// grid: (SPLITS, NKVH, B), block: 256 threads.
// 16 lanes per token, 2 tokens per warp. Lane lg covers dims [lg*4, lg*4+4) and +64.
__global__ void __launch_bounds__(256, 2) k_attn(
    const float* __restrict__ k_in, const float* __restrict__ v_in,
    const int*   __restrict__ bt,
    const float* __restrict__ kc,   const float* __restrict__ vc)
{
    int split = blockIdx.x, h = blockIdx.y, b = blockIdx.z;
    int tid  = threadIdx.x;
    int warp = tid >> 5, lane = tid & 31;
    int half = lane >> 4, lg = lane & 15;

    __shared__ int   sm_bt[BPS];
    __shared__ float sm_m[16][GG], sm_l[16][GG];
    __shared__ __align__(16) float sm_acc[16][GG][HD];   // 32 KB

    for (int i = tid; i < BPS; i += 256) sm_bt[i] = bt[b * BPS + i];
    __syncthreads();

    int ts = split * PER_SPLIT;
    int te = min(ts + PER_SPLIT, T_TOT);
    int range = te - ts;
    int chunk = (range + 7) >> 3;
    int ws = ts + warp * chunk;
    int we = min(ws + chunk, te);

    // q registers (already roped + scaled)
    const float* qp = d_qrs + (b * NQH + h * GG) * HD;
    float4 ql[GG], qh4[GG];
#pragma unroll
    for (int g = 0; g < GG; g++) {
        ql[g]  = *(const float4*)(qp + g * HD + lg * 4);
        qh4[g] = *(const float4*)(qp + g * HD + 64 + lg * 4);
    }

    float m[GG], l[GG];
    float4 a0[GG], a1[GG];
#pragma unroll
    for (int g = 0; g < GG; g++) {
        m[g] = -1e30f; l[g] = 0.f;
        a0[g] = make_float4(0.f, 0.f, 0.f, 0.f);
        a1[g] = make_float4(0.f, 0.f, 0.f, 0.f);
    }

    for (int tw = ws; tw < we; tw += 2) {
        int t = tw + half;
        bool valid = (t < we);
        int tt = valid ? t : ws;  // safe address for masked lane-group

        const float *kp, *vp;
        int pos;
        if (tt >= T_TOT - 1) {            // current token
            kp = k_in + (b * NKVH + h) * HD;
            vp = v_in + (b * NKVH + h) * HD;
            pos = CUR_POSI;
        } else {
            int blk, off;
            if (tt >= 4080) { blk = sm_bt[288]; off = tt - 4080; }
            else {
                int pb = tt >> 4;
                blk = sm_bt[pb ? (33 + pb) : 0];
                off = tt & 15;
            }
            int tok = blk * 16 + off;
            kp = kc + ((size_t)tok * NKVH + h) * HD;
            vp = vc + ((size_t)tok * NKVH + h) * HD;
            pos = (tt < 16) ? tt : (tt + 10);
        }

        float4 k0 = *(const float4*)(kp + lg * 4);
        float4 k1 = *(const float4*)(kp + 64 + lg * 4);
        float4 v0 = *(const float4*)(vp + lg * 4);
        float4 v1 = *(const float4*)(vp + 64 + lg * 4);
        float4 c  = *(const float4*)(d_cos + pos * 64 + lg * 4);
        float4 s  = *(const float4*)(d_sin + pos * 64 + lg * 4);

        float4 r0, r1;
        r0.x = k0.x * c.x - k1.x * s.x;  r1.x = k1.x * c.x + k0.x * s.x;
        r0.y = k0.y * c.y - k1.y * s.y;  r1.y = k1.y * c.y + k0.y * s.y;
        r0.z = k0.z * c.z - k1.z * s.z;  r1.z = k1.z * c.z + k0.z * s.z;
        r0.w = k0.w * c.w - k1.w * s.w;  r1.w = k1.w * c.w + k0.w * s.w;

        float sum[GG];
#pragma unroll
        for (int g = 0; g < GG; g++) sum[g] = dot8(r0, r1, ql[g], qh4[g]);

#pragma unroll
        for (int st = 1; st < 16; st <<= 1) {
#pragma unroll
            for (int g = 0; g < GG; g++)
                sum[g] += __shfl_xor_sync(0xffffffffu, sum[g], st);
        }

        if (!valid) {
#pragma unroll
            for (int g = 0; g < GG; g++) sum[g] = -3e38f;
        }

#pragma unroll
        for (int g = 0; g < GG; g++) {
            if (sum[g] > m[g]) {                 // rare (~ln T per stream)
                float f = exp2f(m[g] - sum[g]);
                l[g] *= f;
                a0[g].x *= f; a0[g].y *= f; a0[g].z *= f; a0[g].w *= f;
                a1[g].x *= f; a1[g].y *= f; a1[g].z *= f; a1[g].w *= f;
                m[g] = sum[g];
            }
            float p = exp2f(sum[g] - m[g]);
            l[g] += p;
            a0[g].x += p * v0.x; a0[g].y += p * v0.y; a0[g].z += p * v0.z; a0[g].w += p * v0.w;
            a1[g].x += p * v1.x; a1[g].y += p * v1.y; a1[g].z += p * v1.z; a1[g].w += p * v1.w;
        }
    }

    // combine 16 half-warp partials within block
    int hidx = warp * 2 + half;
#pragma unroll
    for (int g = 0; g < GG; g++) {
        *(float4*)&sm_acc[hidx][g][lg * 4]      = a0[g];
        *(float4*)&sm_acc[hidx][g][64 + lg * 4] = a1[g];
    }
    if (lg == 0) {
#pragma unroll
        for (int g = 0; g < GG; g++) { sm_m[hidx][g] = m[g]; sm_l[hidx][g] = l[g]; }
    }
    __syncthreads();

    for (int idx = tid; idx < GG * HD; idx += 256) {
        int g = idx >> 7, d = idx & 127;
        float M = -1e30f;
#pragma unroll
        for (int hh = 0; hh < 16; hh++) M = fmaxf(M, sm_m[hh][g]);
        float val = 0.f, L = 0.f;
#pragma unroll
        for (int hh = 0; hh < 16; hh++) {
            float w = exp2f(sm_m[hh][g] - M);
            val += w * sm_acc[hh][g][d];
            L   += w * sm_l[hh][g];
        }
        int base = ((split * NB_B + b) * NKVH + h) * GG + g;
        d_pacc[base * HD + d] = val;
        if (d == 0) { d_pm[base] = M; d_pl[base] = L; }
    }
}

// ---------------- combine splits -> attn ----------------
__global__ void k_combine() {
    int bh = blockIdx.x;            // b*8 + h
    int b = bh >> 3, h = bh & 7;
    int d = threadIdx.x;            // 0..127
#pragma unroll
    for (int g = 0; g < GG; g++) {
        float M = -1e30f;
#pragma unroll
        for (int s2 = 0; s2 < SPLITS; s2++)
            M = fmaxf(M, d_pm[s2 * 256 + bh * 4 + g]);
        float L = 0.f, val = 0.f;
#pragma unroll
        for (int s2 = 0; s2 < SPLITS; s2++) {
            int base = s2 * 256 + bh * 4 + g;
            float w = exp2f(d_pm[base] - M);
            L   += w * d_pl[base];
            val += w * d_pacc[base * HD + d];
        }
        d_attn[b * 4096 + (h * GG + g) * HD + d] = val / L;
    }
}

// ---------------- out = attn @ W_o, row-split partials ----------------
// grid: (32 col-tiles, RS row-splits), 256 threads. warp = batch, lanes = 128 cols (float4).
__global__ void __launch_bounds__(256) k_gemm(const float* __restrict__ W) {
    int ct = blockIdx.x, rs = blockIdx.y;
    int tid = threadIdx.x;
    int bb = tid >> 5, cg = tid & 31;
    int col = ct * 128 + cg * 4;
    const float* attn_b = d_attn + bb * 4096;
    float4 acc = make_float4(0.f, 0.f, 0.f, 0.f);
    int i0 = rs * 512;
#pragma unroll 4
    for (int i = i0; i < i0 + 512; i++) {
        float a = __ldg(attn_b + i);
        float4 w4 = *(const float4*)(W + (size_t)i * 4096 + col);
        acc.x += a * w4.x; acc.y += a * w4.y; acc.z += a * w4.z; acc.w += a * w4.w;
    }
    *(float4*)(d_gpart + ((size_t)rs * NB_B + bb) * 4096 + col) = acc;
}

__global__ void k_reduce(float* __restrict__ out) {
    int idx = blockIdx.x * blockDim.x + threadIdx.x;  // 0..32767
    float s = 0.f;
#pragma unroll
    for (int r = 0; r < RS; r++) s += d_gpart[r * NB_B * 4096 + idx];
    out[idx] = s;
}

// ---------------- launch ----------------
extern "C" void kernel_launch(void* const* d_in, const int* in_sizes, int n_in,
                              void* d_out, int out_size) {
    const float* q  = (const float*)d_in[0];
    const float* k  = (const float*)d_in[1];
    const float* v  = (const float*)d_in[2];
    const int*   bt = (const int*)  d_in[5];
    const float* kc = (const float*)d_in[6];
    const float* vc = (const float*)d_in[7];
    const float* W  = (const float*)d_in[8];
    float* out = (float*)d_out;

    k_tables<<<512, 512>>>();
    k_qrope<<<NB_B * NQH, 64>>>(q);
    dim3 ga(SPLITS, NKVH, NB_B);
    k_attn<<<ga, 256>>>(k, v, bt, kc, vc);
    k_combine<<<64, 128>>>();
    dim3 gg(32, RS);
    k_gemm<<<gg, 256>>>(W);
    k_reduce<<<64, 512>>>(out);
}